// round 17
// baseline (speedup 1.0000x reference)
#include <cuda_runtime.h>
#include <math.h>

// Problem constants
#define BATCH 8
#define DIM   64
#define HID   128
#define C2    256      // 2*HID
#define IMG_H 128
#define IMG_W 128
#define HW    16384    // 128*128

// Scratch u, INTERLEAVED: g_u2[b][cp][px] holds pair (u[cp], u[cp+128]).
__device__ float g_u2[(size_t)BATCH * HID * HW * 2];
// Scratch g = gelu(x1)*x2, planar (B, HID, HW) fp32 = 64 MiB.
__device__ float g_g[(size_t)BATCH * HID * HW];

// ---------------- packed f32x2 helpers (sm_103a FFMA2) ----------------
__device__ __forceinline__ unsigned long long pk2(float v) {
    unsigned long long r;
    asm("mov.b64 %0, {%1, %1};" : "=l"(r) : "f"(v));
    return r;
}
__device__ __forceinline__ unsigned long long fma2(unsigned long long a,
                                                   unsigned long long b,
                                                   unsigned long long c) {
    unsigned long long d;
    asm("fma.rn.f32x2 %0, %1, %2, %3;" : "=l"(d) : "l"(a), "l"(b), "l"(c));
    return d;
}
__device__ __forceinline__ void upk(unsigned long long v, float& lo, float& hi) {
    asm("mov.b64 {%0, %1}, %2;" : "=f"(lo), "=f"(hi) : "l"(v));
}

// ---------------- cp.async helpers ----------------
__device__ __forceinline__ void cp16(void* smem_dst, const void* gmem_src, int src_sz) {
    unsigned int s = (unsigned int)__cvta_generic_to_shared(smem_dst);
    asm volatile("cp.async.ca.shared.global [%0], [%1], 16, %2;\n"
                 :: "r"(s), "l"(gmem_src), "r"(src_sz));
}
__device__ __forceinline__ void cp_commit() {
    asm volatile("cp.async.commit_group;\n");
}
template <int N>
__device__ __forceinline__ void cp_wait() {
    asm volatile("cp.async.wait_group %0;\n" :: "n"(N));
}

// 16B-chunk XOR swizzles (conflict-free stride-32B/64B access)
__device__ __forceinline__ int swz4(int c) { return c ^ ((c >> 3) & 3); }  // 512B row
__device__ __forceinline__ int swz8(int c) { return c ^ ((c >> 3) & 7); }  // 1024B+ row

// =====================================================================
// Kernel 1 (round-12, proven 99.6us): u = W_in * x, interleaved store.
// FULL-K prefetch, unduplicated weights, single barrier. 64KB dyn smem.
// =====================================================================
__global__ void __launch_bounds__(256, 2) k_proj_in(const float* __restrict__ x,
                                                    const float* __restrict__ W_in) {
    extern __shared__ float smem1[];
    float* xs  = smem1;            // [64][128 swizzled]  32768 B
    float* Wsa = smem1 + 8192;     // [64][64]            16384 B
    float* Wsb = smem1 + 12288;    // [64][64]            16384 B

    const int t   = threadIdx.x;
    const int b   = blockIdx.z;
    const int cp0 = blockIdx.y * 64;
    const int p0  = blockIdx.x * 128;

    const int tx = t & 15;
    const int ty = t >> 4;
    const int pb = tx * 8;
    const int q0 = swz4(2 * tx) * 4;
    const int q1 = swz4(2 * tx + 1) * 4;

    float4 wva[4], wvb[4];
#pragma unroll
    for (int i = 0; i < 4; i++) {
        int idx = t + i * 256;
        int j   = idx & 63;
        int kq  = idx >> 6;
        wva[i] = *(const float4*)&W_in[(cp0 + j) * 64 + kq * 4];
        wvb[i] = *(const float4*)&W_in[(cp0 + 128 + j) * 64 + kq * 4];
    }
    const float* xg = x + ((size_t)b * DIM) * HW + p0;
#pragma unroll
    for (int i = 0; i < 8; i++) {
        int idx = t + i * 256;
        int kk  = idx >> 5;
        int c4  = idx & 31;
        cp16(&xs[(kk * 32 + swz4(c4)) * 4], xg + (size_t)kk * HW + c4 * 4, 16);
    }
    cp_commit();
#pragma unroll
    for (int i = 0; i < 4; i++) {
        int idx = t + i * 256;
        int j   = idx & 63;
        int kq  = idx >> 6;
        Wsa[(kq * 4 + 0) * 64 + j] = wva[i].x;
        Wsa[(kq * 4 + 1) * 64 + j] = wva[i].y;
        Wsa[(kq * 4 + 2) * 64 + j] = wva[i].z;
        Wsa[(kq * 4 + 3) * 64 + j] = wva[i].w;
        Wsb[(kq * 4 + 0) * 64 + j] = wvb[i].x;
        Wsb[(kq * 4 + 1) * 64 + j] = wvb[i].y;
        Wsb[(kq * 4 + 2) * 64 + j] = wvb[i].z;
        Wsb[(kq * 4 + 3) * 64 + j] = wvb[i].w;
    }
    cp_wait<0>();
    __syncthreads();                      // the ONLY barrier

    unsigned long long aa[4][4], ab[4][4];
#pragma unroll
    for (int i = 0; i < 4; i++)
#pragma unroll
        for (int j = 0; j < 4; j++) { aa[i][j] = 0ull; ab[i][j] = 0ull; }

#pragma unroll 8
    for (int kk = 0; kk < 64; kk++) {
        float4 wa = *(const float4*)&Wsa[kk * 64 + 4 * ty];
        float4 wb = *(const float4*)&Wsb[kk * 64 + 4 * ty];
        ulonglong2 xv0 = *(const ulonglong2*)(xs + kk * 128 + q0);
        ulonglong2 xv1 = *(const ulonglong2*)(xs + kk * 128 + q1);
        unsigned long long wa0 = pk2(wa.x), wa1 = pk2(wa.y),
                           wa2 = pk2(wa.z), wa3 = pk2(wa.w);
        unsigned long long wb0 = pk2(wb.x), wb1 = pk2(wb.y),
                           wb2 = pk2(wb.z), wb3 = pk2(wb.w);

        aa[0][0] = fma2(wa0, xv0.x, aa[0][0]);
        aa[0][1] = fma2(wa0, xv0.y, aa[0][1]);
        aa[0][2] = fma2(wa0, xv1.x, aa[0][2]);
        aa[0][3] = fma2(wa0, xv1.y, aa[0][3]);
        aa[1][0] = fma2(wa1, xv0.x, aa[1][0]);
        aa[1][1] = fma2(wa1, xv0.y, aa[1][1]);
        aa[1][2] = fma2(wa1, xv1.x, aa[1][2]);
        aa[1][3] = fma2(wa1, xv1.y, aa[1][3]);
        aa[2][0] = fma2(wa2, xv0.x, aa[2][0]);
        aa[2][1] = fma2(wa2, xv0.y, aa[2][1]);
        aa[2][2] = fma2(wa2, xv1.x, aa[2][2]);
        aa[2][3] = fma2(wa2, xv1.y, aa[2][3]);
        aa[3][0] = fma2(wa3, xv0.x, aa[3][0]);
        aa[3][1] = fma2(wa3, xv0.y, aa[3][1]);
        aa[3][2] = fma2(wa3, xv1.x, aa[3][2]);
        aa[3][3] = fma2(wa3, xv1.y, aa[3][3]);

        ab[0][0] = fma2(wb0, xv0.x, ab[0][0]);
        ab[0][1] = fma2(wb0, xv0.y, ab[0][1]);
        ab[0][2] = fma2(wb0, xv1.x, ab[0][2]);
        ab[0][3] = fma2(wb0, xv1.y, ab[0][3]);
        ab[1][0] = fma2(wb1, xv0.x, ab[1][0]);
        ab[1][1] = fma2(wb1, xv0.y, ab[1][1]);
        ab[1][2] = fma2(wb1, xv1.x, ab[1][2]);
        ab[1][3] = fma2(wb1, xv1.y, ab[1][3]);
        ab[2][0] = fma2(wb2, xv0.x, ab[2][0]);
        ab[2][1] = fma2(wb2, xv0.y, ab[2][1]);
        ab[2][2] = fma2(wb2, xv1.x, ab[2][2]);
        ab[2][3] = fma2(wb2, xv1.y, ab[2][3]);
        ab[3][0] = fma2(wb3, xv0.x, ab[3][0]);
        ab[3][1] = fma2(wb3, xv0.y, ab[3][1]);
        ab[3][2] = fma2(wb3, xv1.x, ab[3][2]);
        ab[3][3] = fma2(wb3, xv1.y, ab[3][3]);
    }

#pragma unroll
    for (int ci = 0; ci < 4; ci++) {
        int cp = cp0 + 4 * ty + ci;
        float* base = g_u2 + (((size_t)b * HID + cp) * HW + p0 + pb) * 2;
#pragma unroll
        for (int j = 0; j < 4; j++) {
            float alo, ahi, blo, bhi;
            upk(aa[ci][j], alo, ahi);
            upk(ab[ci][j], blo, bhi);
            *(float4*)(base + 4 * j) = make_float4(alo, blo, ahi, bhi);
        }
    }
}

// =====================================================================
// Kernel 2a (round-12, proven): depthwise 3x3 + exact GELU gate -> g.
// =====================================================================
#define AROW 264
__global__ void __launch_bounds__(256) k_conv_gelu(const float* __restrict__ genk,
                                                   const float* __restrict__ dwkg,
                                                   const float* __restrict__ lam) {
    __shared__ float halo[34 * AROW];     // 35904 B
    __shared__ float kc2s[18];

    const int t  = threadIdx.x;
    const int cp = blockIdx.x;            // channel pair 0..127
    const int rb = blockIdx.y;            // row block 0..3
    const int b  = blockIdx.z;
    const int y0 = rb * 32;

    if (t < 18) {
        int tap = t >> 1, br = t & 1;
        int c = cp + br * HID;
        kc2s[tap * 2 + br] = dwkg[c * 9 + tap] + lam[c] * genk[b * (C2 * 9) + c * 9 + tap];
    }
    for (int i = t; i < 272; i += 256) {
        int rr = i >> 3, j = i & 7;
        halo[rr * AROW + ((j < 4) ? j : (256 + j))] = 0.0f;
    }
    {
        const float* src0 = g_u2 + ((size_t)b * HID + cp) * HW * 2;
#pragma unroll
        for (int i = 0; i < 9; i++) {
            int idx = t + i * 256;
            if (idx < 2176) {
                int rr = idx >> 6, ch = idx & 63;
                int gy = y0 - 1 + rr;
                bool ok = (unsigned)gy < 128u;
                cp16(&halo[rr * AROW + swz8(1 + ch) * 4],
                     src0 + (size_t)(ok ? gy : 0) * 256 + ch * 4, ok ? 16 : 0);
            }
        }
        cp_commit();
    }
    cp_wait<0>();
    __syncthreads();

    unsigned long long tap[9];
#pragma unroll
    for (int i = 0; i < 9; i++) tap[i] = *(const unsigned long long*)&kc2s[2 * i];

    const int s  = t & 15;
    const int x0 = s * 8;
    const int yb = t >> 4;
    int qof[6];
#pragma unroll
    for (int j = 0; j < 6; j++) qof[j] = swz8(4 * s + j) * 4;

    float* gbase = g_g + ((size_t)b * HID + cp) * HW;

#pragma unroll
    for (int half = 0; half < 2; half++) {
        int y = yb + half * 16;
        unsigned long long v[8];
#pragma unroll
        for (int j = 0; j < 8; j++) v[j] = 0ull;

#pragma unroll
        for (int r = 0; r < 3; r++) {
            const float* Hrow = &halo[(y + r) * AROW];
            unsigned long long p[12];
#pragma unroll
            for (int j = 0; j < 6; j++) {
                ulonglong2 qq = *(const ulonglong2*)&Hrow[qof[j]];
                p[2 * j]     = qq.x;
                p[2 * j + 1] = qq.y;
            }
#pragma unroll
            for (int dx = 0; dx < 3; dx++) {
                unsigned long long tp_ = tap[r * 3 + dx];
#pragma unroll
                for (int j = 0; j < 8; j++)
                    v[j] = fma2(tp_, p[j + dx + 1], v[j]);
            }
        }
        float o8[8];
#pragma unroll
        for (int j = 0; j < 8; j++) {
            float va, vb;
            upk(v[j], va, vb);
            o8[j] = 0.5f * va * (1.0f + erff(va * 0.7071067811865476f)) * vb;
        }
        float* dst = gbase + (y0 + y) * IMG_W + x0;
        *(float4*)dst       = make_float4(o8[0], o8[1], o8[2], o8[3]);
        *(float4*)(dst + 4) = make_float4(o8[4], o8[5], o8[6], o8[7]);
    }
}

// =====================================================================
// Kernel 2b v2: out[b,o,p] = sum_c W_out[o,c] * g[b,c,p]
// RESHAPED: 128-px tiles -> 1024 CTAs (vs 512), 48KB smem, thread tile
// 4o x 8px (16 packed accs, ~80 regs) -> 3 CTAs/SM, 2.3 waves.
// Same double-buffered cp.async pipeline; same k-phase order (bitwise
// identical results).
// =====================================================================
__global__ void __launch_bounds__(256, 3) k_proj_out(const float* __restrict__ W_out,
                                                     float* __restrict__ out) {
    extern __shared__ float smem2[];
    float* gsT = smem2;            // [2][32*128 swz4]  32768 B
    float* Wo  = smem2 + 8192;     // [2][32*64]        16384 B

    const int t  = threadIdx.x;
    const int b  = blockIdx.z;
    const int p0 = blockIdx.x * 128;

    const int tx = t & 15;         // px group (8 px)
    const int ty = t >> 4;         // o group 0..15 (4 o)
    const int pb = tx * 8;
    const int ob = ty * 4;
    const int q0 = swz4(2 * tx) * 4;
    const int q1 = swz4(2 * tx + 1) * 4;

    const float* gb = g_g + ((size_t)b * HID) * HW;

    auto stage_g = [&](int ph, int buf) {
        float* dstb = gsT + buf * 4096;
#pragma unroll
        for (int i = 0; i < 4; i++) {         // 32 ch x 32 chunks = 1024
            int idx = t + i * 256;
            int kk = idx >> 5, ch = idx & 31;
            cp16(&dstb[(kk * 32 + swz4(ch)) * 4],
                 gb + (size_t)(ph * 32 + kk) * HW + p0 + ch * 4, 16);
        }
        cp_commit();
    };
    auto w_ldg = [&](int ph, float* w8) {
#pragma unroll
        for (int i = 0; i < 8; i++) {
            int idx = t + i * 256;
            int kk = idx >> 6, o = idx & 63;
            w8[i] = W_out[o * HID + ph * 32 + kk];
        }
    };
    auto w_sts = [&](int buf, const float* w8) {
        float* dstb = Wo + buf * 2048;
#pragma unroll
        for (int i = 0; i < 8; i++) {
            int idx = t + i * 256;
            int kk = idx >> 6, o = idx & 63;
            dstb[kk * 64 + o] = w8[i];
        }
    };

    unsigned long long acc[4][4];
#pragma unroll
    for (int i = 0; i < 4; i++)
#pragma unroll
        for (int j = 0; j < 4; j++) acc[i][j] = 0ull;

    float wreg[8];
    stage_g(0, 0);
    w_ldg(0, wreg);
    w_sts(0, wreg);
    cp_wait<0>();
    __syncthreads();

#pragma unroll 1
    for (int ph = 0; ph < 4; ph++) {
        const int buf = ph & 1;
        if (ph < 3) {
            stage_g(ph + 1, buf ^ 1);
            w_ldg(ph + 1, wreg);
        }

        const float* gB = gsT + buf * 4096;
        const float* wB = Wo + buf * 2048;
#pragma unroll 8
        for (int kk = 0; kk < 32; kk++) {
            float4 w = *(const float4*)&wB[kk * 64 + ob];
            ulonglong2 gA  = *(const ulonglong2*)&gB[kk * 128 + q0];
            ulonglong2 gBv = *(const ulonglong2*)&gB[kk * 128 + q1];
            unsigned long long wp0 = pk2(w.x), wp1 = pk2(w.y),
                               wp2 = pk2(w.z), wp3 = pk2(w.w);

            acc[0][0] = fma2(wp0, gA.x, acc[0][0]);
            acc[0][1] = fma2(wp0, gA.y, acc[0][1]);
            acc[0][2] = fma2(wp0, gBv.x, acc[0][2]);
            acc[0][3] = fma2(wp0, gBv.y, acc[0][3]);
            acc[1][0] = fma2(wp1, gA.x, acc[1][0]);
            acc[1][1] = fma2(wp1, gA.y, acc[1][1]);
            acc[1][2] = fma2(wp1, gBv.x, acc[1][2]);
            acc[1][3] = fma2(wp1, gBv.y, acc[1][3]);
            acc[2][0] = fma2(wp2, gA.x, acc[2][0]);
            acc[2][1] = fma2(wp2, gA.y, acc[2][1]);
            acc[2][2] = fma2(wp2, gBv.x, acc[2][2]);
            acc[2][3] = fma2(wp2, gBv.y, acc[2][3]);
            acc[3][0] = fma2(wp3, gA.x, acc[3][0]);
            acc[3][1] = fma2(wp3, gA.y, acc[3][1]);
            acc[3][2] = fma2(wp3, gBv.x, acc[3][2]);
            acc[3][3] = fma2(wp3, gBv.y, acc[3][3]);
        }

        if (ph < 3) {
            w_sts(buf ^ 1, wreg);
            cp_wait<0>();
            __syncthreads();
        }
    }

    // Epilogue: 4 o-rows x 8 px
#pragma unroll
    for (int oi = 0; oi < 4; oi++) {
        float* dst = out + ((size_t)b * DIM + (ob + oi)) * HW + p0 + pb;
        ulonglong2 v0, v1;
        v0.x = acc[oi][0]; v0.y = acc[oi][1];
        v1.x = acc[oi][2]; v1.y = acc[oi][3];
        ((ulonglong2*)dst)[0] = v0;
        ((ulonglong2*)dst)[1] = v1;
    }
}

// =====================================================================
// Launch (graph-capturable, no allocs, single stream, serial)
// Inputs: x, gen_kernel, W_in, dw_kernel, lambda_dw, W_out
// =====================================================================
extern "C" void kernel_launch(void* const* d_in, const int* in_sizes, int n_in,
                              void* d_out, int out_size) {
    const float* x     = (const float*)d_in[0];
    const float* genk  = (const float*)d_in[1];
    const float* W_in  = (const float*)d_in[2];
    const float* dwk   = (const float*)d_in[3];
    const float* lam   = (const float*)d_in[4];
    const float* W_out = (const float*)d_in[5];
    float* out = (float*)d_out;

    static int attr_done = 0;
    if (!attr_done) {
        cudaFuncSetAttribute(k_proj_in,  cudaFuncAttributeMaxDynamicSharedMemorySize, 65536);
        cudaFuncSetAttribute(k_proj_out, cudaFuncAttributeMaxDynamicSharedMemorySize, 49152);
        attr_done = 1;
    }

    dim3 g1(HW / 128, HID / 64, BATCH);     // (128, 2, 8) = 2048 CTAs
    k_proj_in<<<g1, 256, 65536>>>(x, W_in);

    dim3 g2(HID, IMG_H / 32, BATCH);        // (128, 4, 8) = 4096 CTAs
    k_conv_gelu<<<g2, 256>>>(genk, dwk, lam);

    dim3 g3(HW / 128, 1, BATCH);            // (128, 1, 8) = 1024 CTAs
    k_proj_out<<<g3, 256, 49152>>>(W_out, out);
}